// round 4
// baseline (speedup 1.0000x reference)
#include <cuda_runtime.h>
#include <cuda_bf16.h>

#define NT   160
#define KC   16
#define WPAD 210
#define WBUF (KC*WPAD)   // 3360 floats per W buffer
#define TBUF (KC*64)     // 1024 u64 entries per T buffer

typedef unsigned long long u64;

// ---- packed f32x2 helpers (sm_100a; ptxas never emits FFMA2 from C++) ----
__device__ __forceinline__ u64 ffma2(u64 a, u64 b, u64 c) {
    u64 d;
    asm("fma.rn.f32x2 %0, %1, %2, %3;" : "=l"(d) : "l"(a), "l"(b), "l"(c));
    return d;
}
__device__ __forceinline__ u64 pack2(float x, float y) {
    u64 d;
    asm("mov.b64 %0, {%1, %2};" : "=l"(d) : "f"(x), "f"(y));
    return d;
}
__device__ __forceinline__ void unpack2(u64 d, float& x, float& y) {
    asm("mov.b64 {%0, %1}, %2;" : "=f"(x), "=f"(y) : "l"(d));
}

// One layer: Y[200][64] = relu(W[200][K] @ T[K][64] + bias), T[c][d] = v[m][d]*src[n][d],
// c = m*Nh + n. First 100 rows -> h (next layer's src) unless LAST; direct rows summed
// over d into out.
// Thread tile: 10 o (og = tid>>3, o = og*10..og*10+9) x 8 d (dgr = tid&7, d = dgr*8..dgr*8+7).
template<int K, int Nh, int OUT_OFF, bool LAST>
__device__ __forceinline__ void layer_run(
    const float* __restrict__ Wg, const float* __restrict__ bg,
    float* __restrict__ v, float* __restrict__ h,
    float* __restrict__ Wt, u64* __restrict__ TS,
    float* __restrict__ out, int b, int tid)
{
    const int og  = tid >> 3;   // 0..19
    const int dgr = tid & 7;    // 0..7
    const float* src = (Nh == 40) ? v : h;

    u64 acc[8][5];              // acc[dd][jp] : d = dgr*8+dd, o pair = og*10 + 2*jp {lo,hi}
    #pragma unroll
    for (int dd = 0; dd < 8; dd++)
        #pragma unroll
        for (int jp = 0; jp < 5; jp++) acc[dd][jp] = 0ull;

    constexpr int NCH = K / KC;

    // ---- stage chunk 0 into buffer 0 ----
    {
        // W: 200 o x 16 kk = 3200 floats = 160 threads x 5 LDG.128
        float4 wreg[5];
        #pragma unroll
        for (int i = 0; i < 5; i++) {
            int e = tid + i*NT;               // 0..799
            int o = e >> 2, q = e & 3;        // q = k-quad
            wreg[i] = *reinterpret_cast<const float4*>(Wg + o*K + q*4);
        }
        // T chunk 0: splatted pairs
        for (int idx = tid; idx < TBUF; idx += NT) {
            int kk = idx >> 6, d = idx & 63;
            int c  = kk;
            int m = c / Nh, n = c % Nh;
            float p = v[m*64 + d] * src[n*64 + d];
            TS[idx] = pack2(p, p);
        }
        #pragma unroll
        for (int i = 0; i < 5; i++) {
            int e = tid + i*NT;
            int o = e >> 2, q = e & 3;
            Wt[(q*4 + 0)*WPAD + o] = wreg[i].x;
            Wt[(q*4 + 1)*WPAD + o] = wreg[i].y;
            Wt[(q*4 + 2)*WPAD + o] = wreg[i].z;
            Wt[(q*4 + 3)*WPAD + o] = wreg[i].w;
        }
    }
    __syncthreads();

    for (int kc = 0; kc < NCH; kc++) {
        const int cur = kc & 1, nxt = cur ^ 1;
        const bool more = (kc + 1) < NCH;

        // issue next chunk's global W loads early; latency hidden by compute below
        float4 wreg[5];
        if (more) {
            const int k0n = (kc + 1) * KC;
            #pragma unroll
            for (int i = 0; i < 5; i++) {
                int e = tid + i*NT;
                int o = e >> 2, q = e & 3;
                wreg[i] = *reinterpret_cast<const float4*>(Wg + o*K + k0n + q*4);
            }
        }

        // ---- compute current chunk: per kk: 5 LDS.64 (w) + 4 LDS.128 (t) + 40 FFMA2 ----
        const float* Wc = Wt + cur*WBUF;
        const ulonglong2* Tc2 = reinterpret_cast<const ulonglong2*>(TS + cur*TBUF);
        #pragma unroll
        for (int kk = 0; kk < KC; kk++) {
            const u64* wp = reinterpret_cast<const u64*>(Wc + kk*WPAD + og*10);
            u64 w[5];
            #pragma unroll
            for (int jp = 0; jp < 5; jp++) w[jp] = wp[jp];
            const ulonglong2* tp = Tc2 + kk*32 + dgr*4;
            ulonglong2 t2[4];
            #pragma unroll
            for (int i = 0; i < 4; i++) t2[i] = tp[i];
            #pragma unroll
            for (int i = 0; i < 4; i++) {
                #pragma unroll
                for (int jp = 0; jp < 5; jp++)
                    acc[2*i][jp] = ffma2(w[jp], t2[i].x, acc[2*i][jp]);
                #pragma unroll
                for (int jp = 0; jp < 5; jp++)
                    acc[2*i+1][jp] = ffma2(w[jp], t2[i].y, acc[2*i+1][jp]);
            }
        }

        // ---- stage next chunk into the other buffer ----
        if (more) {
            const int k0n = (kc + 1) * KC;
            u64* Tn = TS + nxt*TBUF;
            for (int idx = tid; idx < TBUF; idx += NT) {
                int kk = idx >> 6, d = idx & 63;
                int c  = k0n + kk;
                int m = c / Nh, n = c % Nh;
                float p = v[m*64 + d] * src[n*64 + d];
                Tn[idx] = pack2(p, p);
            }
            float* Wn = Wt + nxt*WBUF;
            #pragma unroll
            for (int i = 0; i < 5; i++) {
                int e = tid + i*NT;
                int o = e >> 2, q = e & 3;
                Wn[(q*4 + 0)*WPAD + o] = wreg[i].x;
                Wn[(q*4 + 1)*WPAD + o] = wreg[i].y;
                Wn[(q*4 + 2)*WPAD + o] = wreg[i].z;
                Wn[(q*4 + 3)*WPAD + o] = wreg[i].w;
            }
        }
        __syncthreads();
    }

    // ---- epilogue: bias + relu, write h, reduce over d, write direct outputs ----
    float y[8][10];
    #pragma unroll
    for (int jp = 0; jp < 5; jp++) {
        float blo = bg[og*10 + 2*jp];
        float bhi = bg[og*10 + 2*jp + 1];
        #pragma unroll
        for (int dd = 0; dd < 8; dd++) {
            float lo, hi;
            unpack2(acc[dd][jp], lo, hi);
            y[dd][2*jp]     = fmaxf(lo + blo, 0.0f);
            y[dd][2*jp + 1] = fmaxf(hi + bhi, 0.0f);
        }
    }
    if (!LAST && og < 10) {           // rows 0..99 become next hidden
        #pragma unroll
        for (int j = 0; j < 10; j++) {
            float2* hp = reinterpret_cast<float2*>(h + (og*10 + j)*64 + dgr*8);
            #pragma unroll
            for (int p = 0; p < 4; p++)
                hp[p] = make_float2(y[2*p][j], y[2*p+1][j]);
        }
    }
    #pragma unroll
    for (int j = 0; j < 10; j++) {    // sum over the 64 d values (8 local + 8 lanes)
        float s = 0.0f;
        #pragma unroll
        for (int dd = 0; dd < 8; dd++) s += y[dd][j];
        s += __shfl_xor_sync(0xFFFFFFFFu, s, 4);
        s += __shfl_xor_sync(0xFFFFFFFFu, s, 2);
        s += __shfl_xor_sync(0xFFFFFFFFu, s, 1);
        if (dgr == 0) {
            int o = og*10 + j;
            if (LAST)          out[b*400 + 200 + o] = s;
            else if (o >= 100) out[b*400 + OUT_OFF + (o - 100)] = s;
        }
    }
    __syncthreads();   // h fully written before next layer stages T from it
}

__global__ void __launch_bounds__(NT, 2)
_CIN_41575283425691_kernel(const float* __restrict__ x,
                           const float* __restrict__ w1, const float* __restrict__ b1,
                           const float* __restrict__ w2, const float* __restrict__ b2,
                           const float* __restrict__ w3, const float* __restrict__ b3,
                           float* __restrict__ out)
{
    extern __shared__ float sm[];
    float* v  = sm;                                    // 40 x 64            = 2560 f
    float* h  = sm + 2560;                             // 100 x 64           = 6400 f
    float* Wt = sm + 8960;                             // 2 x 16 x 210       = 6720 f
    u64*  TS  = reinterpret_cast<u64*>(sm + 15680);    // 2 x 1024 x 8B      = 16384 B (16B aligned)

    const int tid = threadIdx.x;
    const int b   = blockIdx.x;

    const float* xb = x + b*2560;
    for (int i = tid; i < 2560; i += NT) v[i] = xb[i];
    __syncthreads();

    layer_run<1600,  40,   0, false>(w1, b1, v, h, Wt, TS, out, b, tid);
    layer_run<4000, 100, 100, false>(w2, b2, v, h, Wt, TS, out, b, tid);
    layer_run<4000, 100,   0, true >(w3, b3, v, h, Wt, TS, out, b, tid);
}

#define SMEM_BYTES 79104   // 15680 floats + 16384 B = 62720 + 16384

extern "C" void kernel_launch(void* const* d_in, const int* in_sizes, int n_in,
                              void* d_out, int out_size)
{
    const float* x  = (const float*)d_in[0];
    const float* w1 = (const float*)d_in[1];
    const float* b1 = (const float*)d_in[2];
    const float* w2 = (const float*)d_in[3];
    const float* b2 = (const float*)d_in[4];
    const float* w3 = (const float*)d_in[5];
    const float* b3 = (const float*)d_in[6];
    float* out = (float*)d_out;

    cudaFuncSetAttribute(_CIN_41575283425691_kernel,
                         cudaFuncAttributeMaxDynamicSharedMemorySize, SMEM_BYTES);
    _CIN_41575283425691_kernel<<<512, NT, SMEM_BYTES>>>(x, w1, b1, w2, b2, w3, b3, out);
}

// round 5
// speedup vs baseline: 5.3553x; 5.3553x over previous
#include <cuda_runtime.h>
#include <cstdint>

#define NT    416          // 13 warps = 13 o-tiles of 16 (O=200 padded to 208)
#define KC    32           // K chunk (4 k8 steps per chunk)
#define OP    208
#define KP    36           // W chunk row stride (floats): bank-free A loads, 16B aligned
#define DP    72           // T row stride (floats): bank-free B loads, 16B aligned
#define WCBUF (OP*KP)      // 7488 floats per W buffer
#define TBUF  (KC*DP)      // 2304 floats per T buffer
#define VOFF  0            // v: 40x64        = 2560 floats
#define HOFF  2560         // h: 100x64       = 6400 floats
#define WOFF  8960         // Wc: 2 x 7488
#define TOFF  (8960 + 2*WCBUF)          // 23936
#define SMEMF (TOFF + 2*TBUF)           // 28544 floats = 114176 B
#define VSCALE 1.0001691f  // 1 + 0.5*ln2*2^-11 : centers tf32 RZ-truncation bias of T

__device__ __forceinline__ float tf32r(float x) {   // round-to-nearest tf32
    uint32_t u;
    asm("cvt.rna.tf32.f32 %0, %1;" : "=r"(u) : "f"(x));
    return __uint_as_float(u);
}

__device__ __forceinline__ void mma_tf32(float* c, const uint32_t a[4],
                                         uint32_t b0, uint32_t b1) {
    asm volatile(
        "mma.sync.aligned.m16n8k8.row.col.f32.tf32.tf32.f32 "
        "{%0,%1,%2,%3}, {%4,%5,%6,%7}, {%8,%9}, {%0,%1,%2,%3};"
        : "+f"(c[0]), "+f"(c[1]), "+f"(c[2]), "+f"(c[3])
        : "r"(a[0]), "r"(a[1]), "r"(a[2]), "r"(a[3]), "r"(b0), "r"(b1));
}

// Build T chunk [KC x 64] into buffer: T[cc][d] = v[m][d]*src[n][d], c = k0+cc = m*Nh+n.
template<int Nh>
__device__ __forceinline__ void build_T(const float* __restrict__ v,
                                        const float* __restrict__ src,
                                        float* __restrict__ Tb, int k0, int tid)
{
    const float4* v4 = reinterpret_cast<const float4*>(v);
    const float4* s4 = reinterpret_cast<const float4*>(src);
    for (int t = tid; t < KC*16; t += NT) {      // 512 quad-tasks
        int cc = t >> 4, dq = t & 15;
        int c = k0 + cc;
        int m = c / Nh, n = c - m*Nh;
        float4 a = v4[m*16 + dq];
        float4 b = s4[n*16 + dq];
        float4 p;
        p.x = a.x*b.x; p.y = a.y*b.y; p.z = a.z*b.z; p.w = a.w*b.w;
        *reinterpret_cast<float4*>(Tb + cc*DP + dq*4) = p;
    }
}

// One layer. Warp wid owns o-tile rows [wid*16, wid*16+16). C frags cover all 8 d-tiles.
template<int K, int Nh, int OUT_OFF, bool LAST>
__device__ __forceinline__ void layer_run(
    const float* __restrict__ Wg, const float* __restrict__ bg,
    float* __restrict__ S, float* __restrict__ out, int b, int tid)
{
    float* v = S + VOFF;
    float* h = S + HOFF;
    const float* src = (Nh == 40) ? v : h;
    const int lane = tid & 31, wid = tid >> 5;
    const int g = lane >> 2, tig = lane & 3;
    const int o0 = wid * 16;

    float c[8][4];
    #pragma unroll
    for (int j = 0; j < 8; j++)
        #pragma unroll
        for (int r = 0; r < 4; r++) c[j][r] = 0.0f;

    constexpr int NCH = K / KC;

    // ---- stage chunk 0 (buffer 0) ----
    {
        #pragma unroll
        for (int i = 0; i < 4; i++) {
            int e = tid + i*NT;                   // 1664 = 208 o x 8 quads
            int o = e >> 3, q = e & 7;
            float4 w = make_float4(0.f, 0.f, 0.f, 0.f);
            if (o < 200) w = *reinterpret_cast<const float4*>(Wg + o*K + q*4);
            w.x = tf32r(w.x); w.y = tf32r(w.y); w.z = tf32r(w.z); w.w = tf32r(w.w);
            *reinterpret_cast<float4*>(S + WOFF + o*KP + q*4) = w;
        }
        build_T<Nh>(v, src, S + TOFF, 0, tid);
    }
    __syncthreads();

    for (int kc = 0; kc < NCH; kc++) {
        const int cur = kc & 1, nxt = cur ^ 1;
        const bool more = (kc + 1) < NCH;

        // prefetch next W chunk into regs (L2 latency hidden by MMA below)
        float4 wpre[4];
        if (more) {
            const int k0n = (kc + 1) * KC;
            #pragma unroll
            for (int i = 0; i < 4; i++) {
                int e = tid + i*NT;
                int o = e >> 3, q = e & 7;
                wpre[i] = make_float4(0.f, 0.f, 0.f, 0.f);
                if (o < 200)
                    wpre[i] = *reinterpret_cast<const float4*>(Wg + o*K + k0n + q*4);
            }
        }

        // ---- MMA on current chunk: 4 k8-steps x 8 d-tiles ----
        const uint32_t* Wc = reinterpret_cast<const uint32_t*>(S + WOFF + cur*WCBUF);
        const uint32_t* Tc = reinterpret_cast<const uint32_t*>(S + TOFF + cur*TBUF);
        #pragma unroll
        for (int kq = 0; kq < 4; kq++) {
            const int col = kq*8 + tig;
            uint32_t a[4];
            a[0] = Wc[(o0 + g    )*KP + col    ];
            a[1] = Wc[(o0 + g + 8)*KP + col    ];
            a[2] = Wc[(o0 + g    )*KP + col + 4];
            a[3] = Wc[(o0 + g + 8)*KP + col + 4];
            const uint32_t* Tr0 = Tc + (kq*8 + tig    )*DP + g;
            const uint32_t* Tr1 = Tc + (kq*8 + tig + 4)*DP + g;
            #pragma unroll
            for (int j = 0; j < 8; j++)
                mma_tf32(c[j], a, Tr0[j*8], Tr1[j*8]);
        }

        // ---- stage next chunk ----
        if (more) {
            build_T<Nh>(v, src, S + TOFF + nxt*TBUF, (kc + 1)*KC, tid);
            float* Wn = S + WOFF + nxt*WCBUF;
            #pragma unroll
            for (int i = 0; i < 4; i++) {
                int e = tid + i*NT;
                int o = e >> 3, q = e & 7;
                float4 w = wpre[i];
                w.x = tf32r(w.x); w.y = tf32r(w.y); w.z = tf32r(w.z); w.w = tf32r(w.w);
                *reinterpret_cast<float4*>(Wn + o*KP + q*4) = w;
            }
        }
        __syncthreads();
    }

    // ---- epilogue: bias+relu, h write (rows<100), d-sum, direct outputs ----
    const int r0 = o0 + g, r1 = o0 + g + 8;
    const float b0v = (r0 < 200) ? bg[r0] : 0.0f;
    const float b1v = (r1 < 200) ? bg[r1] : 0.0f;
    float s0 = 0.0f, s1 = 0.0f;
    #pragma unroll
    for (int j = 0; j < 8; j++) {
        float y00 = fmaxf(c[j][0] + b0v, 0.0f);
        float y01 = fmaxf(c[j][1] + b0v, 0.0f);
        float y10 = fmaxf(c[j][2] + b1v, 0.0f);
        float y11 = fmaxf(c[j][3] + b1v, 0.0f);
        if (!LAST) {
            int d = j*8 + 2*tig;
            if (r0 < 100) { h[r0*64 + d] = y00; h[r0*64 + d + 1] = y01; }
            if (r1 < 100) { h[r1*64 + d] = y10; h[r1*64 + d + 1] = y11; }
        }
        s0 += y00 + y01;
        s1 += y10 + y11;
    }
    s0 += __shfl_xor_sync(0xFFFFFFFFu, s0, 1);
    s0 += __shfl_xor_sync(0xFFFFFFFFu, s0, 2);
    s1 += __shfl_xor_sync(0xFFFFFFFFu, s1, 1);
    s1 += __shfl_xor_sync(0xFFFFFFFFu, s1, 2);
    if (tig == 0) {
        if (LAST) {
            if (r0 < 200) out[b*400 + 200 + r0] = s0;
            if (r1 < 200) out[b*400 + 200 + r1] = s1;
        } else {
            if (r0 >= 100 && r0 < 200) out[b*400 + OUT_OFF + (r0 - 100)] = s0;
            if (r1 >= 100 && r1 < 200) out[b*400 + OUT_OFF + (r1 - 100)] = s1;
        }
    }
    __syncthreads();   // h complete before next layer builds T from it
}

__global__ void __launch_bounds__(NT, 2)
_CIN_41575283425691_kernel(const float* __restrict__ x,
                           const float* __restrict__ w1, const float* __restrict__ b1,
                           const float* __restrict__ w2, const float* __restrict__ b2,
                           const float* __restrict__ w3, const float* __restrict__ b3,
                           float* __restrict__ out)
{
    extern __shared__ float S[];
    const int tid = threadIdx.x;
    const int b   = blockIdx.x;

    // v = x * VSCALE (centers tf32 truncation bias of the on-the-fly products)
    const float* xb = x + b*2560;
    for (int i = tid; i < 2560; i += NT) S[VOFF + i] = xb[i] * VSCALE;
    __syncthreads();

    layer_run<1600,  40,   0, false>(w1, b1, S, out, b, tid);
    layer_run<4000, 100, 100, false>(w2, b2, S, out, b, tid);
    layer_run<4000, 100,   0, true >(w3, b3, S, out, b, tid);
}

#define SMEM_BYTES (SMEMF * 4)   // 114176

extern "C" void kernel_launch(void* const* d_in, const int* in_sizes, int n_in,
                              void* d_out, int out_size)
{
    const float* x  = (const float*)d_in[0];
    const float* w1 = (const float*)d_in[1];
    const float* b1 = (const float*)d_in[2];
    const float* w2 = (const float*)d_in[3];
    const float* b2 = (const float*)d_in[4];
    const float* w3 = (const float*)d_in[5];
    const float* b3 = (const float*)d_in[6];
    float* out = (float*)d_out;

    cudaFuncSetAttribute(_CIN_41575283425691_kernel,
                         cudaFuncAttributeMaxDynamicSharedMemorySize, SMEM_BYTES);
    _CIN_41575283425691_kernel<<<512, NT, SMEM_BYTES>>>(x, w1, b1, w2, b2, w3, b3, out);
}

// round 8
// speedup vs baseline: 10.1781x; 1.9006x over previous
#include <cuda_runtime.h>
#include <cuda_fp16.h>
#include <cstdint>

#define NT   224
#define KC   32
#define WSZ  14336                 // 224 rows x 64B, one W chunk tile
#define TSZ  4096                  // 64 rows x 64B, one T chunk tile

// smem byte map
#define OFF_V  0                   // v: 2560 f32 (stride 64)        = 10240
#define OFF_H  10240               // h: 100 x 72 f32 (padded)       = 28800
#define OFF_W  39040               // 2 x WSZ (128B aligned)
#define OFF_T  (OFF_W + 2*WSZ)     // 67712 (128B aligned)
#define SMEM_BYTES (OFF_T + 2*TSZ) // 75904

// Pre-converted W: 300 chunks x 896 uint4 (14336B each), swizzled+permuted fp16
__device__ uint4 g_w16[300 * 896];

static __device__ __forceinline__ uint32_t smem_u32(const void* p) {
    uint32_t a;
    asm("{ .reg .u64 t; cvta.to.shared.u64 t, %1; cvt.u32.u64 %0, t; }" : "=r"(a) : "l"(p));
    return a;
}
static __device__ __forceinline__ void lds64(uint32_t& x, uint32_t& y, uint32_t a) {
    asm volatile("ld.shared.v2.b32 {%0,%1}, [%2];" : "=r"(x), "=r"(y) : "r"(a));
}
static __device__ __forceinline__ void sts128(uint32_t a, uint4 v) {
    asm volatile("st.shared.v4.b32 [%0], {%1,%2,%3,%4};"
                 :: "r"(a), "r"(v.x), "r"(v.y), "r"(v.z), "r"(v.w));
}
static __device__ __forceinline__ void mma16816(float* c, uint32_t a0, uint32_t a1,
                                                uint32_t a2, uint32_t a3,
                                                uint32_t b0, uint32_t b1) {
    asm volatile(
        "mma.sync.aligned.m16n8k16.row.col.f32.f16.f16.f32 "
        "{%0,%1,%2,%3}, {%4,%5,%6,%7}, {%8,%9}, {%0,%1,%2,%3};"
        : "+f"(c[0]), "+f"(c[1]), "+f"(c[2]), "+f"(c[3])
        : "r"(a0), "r"(a1), "r"(a2), "r"(a3), "r"(b0), "r"(b1));
}
static __device__ __forceinline__ uint32_t h2u(__half2 h) {
    return *reinterpret_cast<uint32_t*>(&h);
}

// ---- prep: W fp32 -> fp16, k-permuted [2t,2t+1,2t+8,2t+9], XOR-swizzled rows ----
__global__ void _CIN_prep_kernel(const float* __restrict__ w1,
                                 const float* __restrict__ w2,
                                 const float* __restrict__ w3) {
    int kcg = blockIdx.x;          // global chunk 0..299
    const float* W; int K, kc;
    if (kcg < 50)       { W = w1; K = 1600; kc = kcg; }
    else if (kcg < 175) { W = w2; K = 4000; kc = kcg - 50; }
    else                { W = w3; K = 4000; kc = kcg - 175; }
    const int kbase = kc * KC;
    uint32_t* dst = reinterpret_cast<uint32_t*>(g_w16 + kcg * 896);
    for (int q = threadIdx.x; q < 1792; q += 256) {   // 224 rows x 8 quads
        int row = q >> 3, kq = (q >> 2) & 1, t = q & 3;
        float p0 = 0.f, p1 = 0.f, p2 = 0.f, p3 = 0.f;
        if (row < 200) {
            const float* s = W + row*K + kbase + kq*16 + 2*t;
            p0 = s[0]; p1 = s[1]; p2 = s[8]; p3 = s[9];
        }
        uint32_t byte = row*64 + (((uint32_t)(kq*32 + 8*t)) ^ (((row >> 1) & 1) << 5));
        dst[(byte >> 2)    ] = h2u(__floats2half2_rn(p0, p1));
        dst[(byte >> 2) + 1] = h2u(__floats2half2_rn(p2, p3));
    }
}

// ---- T chunk build: T[d][k] fp16, rows 64B, same perm+swizzle. 128 threads active ----
template<int Nh, int SRCS>
static __device__ __forceinline__ void build_T(const float* __restrict__ v,
                                               const float* __restrict__ src,
                                               uint32_t tbase, int k0, int tid) {
    if (tid >= 128) return;
    const int d = tid & 63, kq = tid >> 6;
    int cb = k0 + kq*16;
    int m = cb / Nh;
    int n = cb - m*Nh;
    float vm = v[m*64 + d];
    float p[16];
    #pragma unroll
    for (int i = 0; i < 16; i++) {
        if (n == Nh) { n = 0; m++; vm = v[m*64 + d]; }
        p[i] = vm * src[n*SRCS + d];
        n++;
    }
    uint4 q0, q1;   // perm order: [0,1,8,9, 2,3,10,11] [4,5,12,13, 6,7,14,15]
    q0.x = h2u(__floats2half2_rn(p[0],  p[1]));
    q0.y = h2u(__floats2half2_rn(p[8],  p[9]));
    q0.z = h2u(__floats2half2_rn(p[2],  p[3]));
    q0.w = h2u(__floats2half2_rn(p[10], p[11]));
    q1.x = h2u(__floats2half2_rn(p[4],  p[5]));
    q1.y = h2u(__floats2half2_rn(p[12], p[13]));
    q1.z = h2u(__floats2half2_rn(p[6],  p[7]));
    q1.w = h2u(__floats2half2_rn(p[14], p[15]));
    uint32_t a = tbase + d*64 + (((uint32_t)(kq*32)) ^ (((d >> 1) & 1) << 5));
    sts128(a, q0);
    sts128(a + 16, q1);
}

// ---- one layer ----
template<int K, int Nh, int SRCS, int CHUNK0, int OUT_OFF, bool LAST>
static __device__ __forceinline__ void layer_run(
    const float* __restrict__ bg, char* smem, uint32_t smem_base,
    float* __restrict__ out, int b, int tid)
{
    const float* v   = reinterpret_cast<const float*>(smem + OFF_V);
    const float* src = (Nh == 40) ? v : reinterpret_cast<const float*>(smem + OFF_H);
    float* h = reinterpret_cast<float*>(smem + OFF_H);
    constexpr int NCH = K / KC;

    const int lane = tid & 31, w = tid >> 5;
    const int g = lane >> 2, tig = lane & 3;
    const uint32_t s = (uint32_t)(g & 2) << 4;   // row-swizzle bit for this lane
    const int o0 = w * 32;

    float c[2][8][4];
    #pragma unroll
    for (int ot = 0; ot < 2; ot++)
        #pragma unroll
        for (int j = 0; j < 8; j++)
            #pragma unroll
            for (int r = 0; r < 4; r++) c[ot][j][r] = 0.0f;

    // stage chunk 0
    {
        const uint4* gsrc = g_w16 + (size_t)CHUNK0 * 896;
        #pragma unroll
        for (int j = 0; j < 4; j++)
            sts128(smem_base + OFF_W + (tid + j*NT)*16, gsrc[tid + j*NT]);
        build_T<Nh, SRCS>(v, src, smem_base + OFF_T, 0, tid);
    }
    __syncthreads();

    for (int kc = 0; kc < NCH; kc++) {
        const int cur = kc & 1, nxt = cur ^ 1;
        const bool more = (kc + 1) < NCH;

        uint4 wpre[4];
        if (more) {
            const uint4* gsrc = g_w16 + (size_t)(CHUNK0 + kc + 1) * 896;
            #pragma unroll
            for (int j = 0; j < 4; j++) wpre[j] = gsrc[tid + j*NT];
        }

        // MMA on current buffers
        const uint32_t Wb = smem_base + OFF_W + cur*WSZ;
        const uint32_t Tb = smem_base + OFF_T + cur*TSZ;
        #pragma unroll
        for (int kq = 0; kq < 2; kq++) {
            const uint32_t off = (((uint32_t)(kq*32)) ^ s) + 8*tig;
            uint32_t b0[8], b1[8];
            #pragma unroll
            for (int j = 0; j < 8; j++)
                lds64(b0[j], b1[j], Tb + (j*8 + g)*64 + off);
            #pragma unroll
            for (int ot = 0; ot < 2; ot++) {
                const uint32_t r = o0 + ot*16 + g;
                uint32_t a0, a2, a1, a3;
                lds64(a0, a2, Wb + r*64 + off);
                lds64(a1, a3, Wb + (r + 8)*64 + off);
                #pragma unroll
                for (int j = 0; j < 8; j++)
                    mma16816(c[ot][j], a0, a1, a2, a3, b0[j], b1[j]);
            }
        }

        if (more) {
            #pragma unroll
            for (int j = 0; j < 4; j++)
                sts128(smem_base + OFF_W + nxt*WSZ + (tid + j*NT)*16, wpre[j]);
            build_T<Nh, SRCS>(v, src, smem_base + OFF_T + nxt*TSZ, (kc + 1)*KC, tid);
        }
        __syncthreads();
    }

    // epilogue
    #pragma unroll
    for (int ot = 0; ot < 2; ot++) {
        const int r0 = o0 + ot*16 + g, r1 = r0 + 8;
        const float bz0 = (r0 < 200) ? bg[r0] : 0.0f;
        const float bz1 = (r1 < 200) ? bg[r1] : 0.0f;
        float s0 = 0.0f, s1 = 0.0f;
        #pragma unroll
        for (int j = 0; j < 8; j++) {
            float y00 = fmaxf(c[ot][j][0] + bz0, 0.0f);
            float y01 = fmaxf(c[ot][j][1] + bz0, 0.0f);
            float y10 = fmaxf(c[ot][j][2] + bz1, 0.0f);
            float y11 = fmaxf(c[ot][j][3] + bz1, 0.0f);
            if (!LAST) {
                const int d = j*8 + 2*tig;
                if (r0 < 100) *reinterpret_cast<float2*>(h + r0*72 + d) = make_float2(y00, y01);
                if (r1 < 100) *reinterpret_cast<float2*>(h + r1*72 + d) = make_float2(y10, y11);
            }
            s0 += y00 + y01;
            s1 += y10 + y11;
        }
        s0 += __shfl_xor_sync(0xFFFFFFFFu, s0, 1);
        s0 += __shfl_xor_sync(0xFFFFFFFFu, s0, 2);
        s1 += __shfl_xor_sync(0xFFFFFFFFu, s1, 1);
        s1 += __shfl_xor_sync(0xFFFFFFFFu, s1, 2);
        if (tig == 0) {
            if (LAST) {
                if (r0 < 200) out[b*400 + 200 + r0] = s0;
                if (r1 < 200) out[b*400 + 200 + r1] = s1;
            } else {
                if (r0 >= 100 && r0 < 200) out[b*400 + OUT_OFF + (r0 - 100)] = s0;
                if (r1 >= 100 && r1 < 200) out[b*400 + OUT_OFF + (r1 - 100)] = s1;
            }
        }
    }
    __syncthreads();   // h fully written before next layer's build_T reads it
}

__global__ void __launch_bounds__(NT, 2)
_CIN_41575283425691_kernel(const float* __restrict__ x,
                           const float* __restrict__ b1,
                           const float* __restrict__ b2,
                           const float* __restrict__ b3,
                           float* __restrict__ out)
{
    extern __shared__ char smem[];
    const uint32_t smem_base = smem_u32(smem);
    const int tid = threadIdx.x;
    const int b   = blockIdx.x;

    float* v = reinterpret_cast<float*>(smem + OFF_V);
    const float* xb = x + b*2560;
    for (int i = tid; i < 2560; i += NT) v[i] = xb[i];
    __syncthreads();

    layer_run<1600,  40, 64,   0,   0, false>(b1, smem, smem_base, out, b, tid);
    layer_run<4000, 100, 72,  50, 100, false>(b2, smem, smem_base, out, b, tid);
    layer_run<4000, 100, 72, 175,   0, true >(b3, smem, smem_base, out, b, tid);
}

extern "C" void kernel_launch(void* const* d_in, const int* in_sizes, int n_in,
                              void* d_out, int out_size)
{
    const float* x  = (const float*)d_in[0];
    const float* w1 = (const float*)d_in[1];
    const float* b1 = (const float*)d_in[2];
    const float* w2 = (const float*)d_in[3];
    const float* b2 = (const float*)d_in[4];
    const float* w3 = (const float*)d_in[5];
    const float* b3 = (const float*)d_in[6];
    float* out = (float*)d_out;

    _CIN_prep_kernel<<<300, 256>>>(w1, w2, w3);

    cudaFuncSetAttribute(_CIN_41575283425691_kernel,
                         cudaFuncAttributeMaxDynamicSharedMemorySize, SMEM_BYTES);
    _CIN_41575283425691_kernel<<<512, NT, SMEM_BYTES>>>(x, b1, b2, b3, out);
}

// round 9
// speedup vs baseline: 11.9035x; 1.1695x over previous
#include <cuda_runtime.h>
#include <cuda_fp16.h>
#include <cstdint>

#define NT   224
#define KC   32
#define WSZ  14336                 // 224 rows x 64B, one W chunk tile
#define TSZ  4096                  // 64 rows x 64B, one T chunk tile

// smem byte map
#define OFF_V  0                   // v: 2560 f32 (stride 64)        = 10240
#define OFF_H  10240               // h: 100 x 72 f32 (padded)       = 28800
#define OFF_W  39040               // 2 x WSZ (128B aligned)
#define OFF_T  (OFF_W + 2*WSZ)     // 67712 (128B aligned)
#define SMEM_BYTES (OFF_T + 2*TSZ) // 75904

// Pre-converted W: 300 chunks x 896 uint4 (14336B each): fp16, k-linear rows of 64B,
// 16B-block swizzle: byte_col ^= (row & 6) << 3
__device__ uint4 g_w16[300 * 896];

static __device__ __forceinline__ uint32_t smem_u32(const void* p) {
    uint32_t a;
    asm("{ .reg .u64 t; cvta.to.shared.u64 t, %1; cvt.u32.u64 %0, t; }" : "=r"(a) : "l"(p));
    return a;
}
static __device__ __forceinline__ void sts128(uint32_t a, uint4 v) {
    asm volatile("st.shared.v4.b32 [%0], {%1,%2,%3,%4};"
                 :: "r"(a), "r"(v.x), "r"(v.y), "r"(v.z), "r"(v.w));
}
static __device__ __forceinline__ void ldsm4(uint32_t& r0, uint32_t& r1,
                                             uint32_t& r2, uint32_t& r3, uint32_t a) {
    asm volatile("ldmatrix.sync.aligned.m8n8.x4.shared.b16 {%0,%1,%2,%3}, [%4];"
                 : "=r"(r0), "=r"(r1), "=r"(r2), "=r"(r3) : "r"(a));
}
static __device__ __forceinline__ void cpasync16(uint32_t s, const void* g) {
    asm volatile("cp.async.cg.shared.global [%0], [%1], 16;"
                 :: "r"(s), "l"(__cvta_generic_to_global(g)) : "memory");
}
static __device__ __forceinline__ void mma16816(float* c, uint32_t a0, uint32_t a1,
                                                uint32_t a2, uint32_t a3,
                                                uint32_t b0, uint32_t b1) {
    asm volatile(
        "mma.sync.aligned.m16n8k16.row.col.f32.f16.f16.f32 "
        "{%0,%1,%2,%3}, {%4,%5,%6,%7}, {%8,%9}, {%0,%1,%2,%3};"
        : "+f"(c[0]), "+f"(c[1]), "+f"(c[2]), "+f"(c[3])
        : "r"(a0), "r"(a1), "r"(a2), "r"(a3), "r"(b0), "r"(b1));
}
static __device__ __forceinline__ uint32_t h2u(__half2 h) {
    return *reinterpret_cast<uint32_t*>(&h);
}

// ---- prep: W fp32 -> fp16, k-linear 64B rows, 16B-block swizzle ----
__global__ void _CIN_prep_kernel(const float* __restrict__ w1,
                                 const float* __restrict__ w2,
                                 const float* __restrict__ w3) {
    int kcg = blockIdx.x;          // global chunk 0..299
    const float* W; int K, kc;
    if (kcg < 50)       { W = w1; K = 1600; kc = kcg; }
    else if (kcg < 175) { W = w2; K = 4000; kc = kcg - 50; }
    else                { W = w3; K = 4000; kc = kcg - 175; }
    const int kbase = kc * KC;
    char* dst = reinterpret_cast<char*>(g_w16 + kcg * 896);
    for (int q = threadIdx.x; q < 896; q += 256) {   // 224 rows x 4 16B-quads
        int row = q >> 2, qq = q & 3;                // quad qq = k-local 8qq..8qq+7
        uint4 val = make_uint4(0, 0, 0, 0);
        if (row < 200) {
            const float* s = W + row*K + kbase + qq*8;
            val.x = h2u(__floats2half2_rn(s[0], s[1]));
            val.y = h2u(__floats2half2_rn(s[2], s[3]));
            val.z = h2u(__floats2half2_rn(s[4], s[5]));
            val.w = h2u(__floats2half2_rn(s[6], s[7]));
        }
        uint32_t byte = row*64 + (((uint32_t)(qq*16)) ^ (((uint32_t)(row & 6)) << 3));
        *reinterpret_cast<uint4*>(dst + byte) = val;
    }
}

// ---- T chunk build: T[d][k] fp16, k-linear 64B rows, same swizzle. tid<128 active ----
template<int Nh, int SRCS>
static __device__ __forceinline__ void build_T(const float* __restrict__ v,
                                               const float* __restrict__ src,
                                               uint32_t tbase, int k0, int tid) {
    if (tid >= 128) return;
    const int d = tid & 63, kq = tid >> 6;
    int cb = k0 + kq*16;
    int m = cb / Nh;
    int n = cb - m*Nh;
    float vm = v[m*64 + d];
    float p[16];
    #pragma unroll
    for (int i = 0; i < 16; i++) {
        if (n == Nh) { n = 0; m++; vm = v[m*64 + d]; }
        p[i] = vm * src[n*SRCS + d];
        n++;
    }
    uint4 q0, q1;   // linear: k 0..7 | 8..15 of this kq half
    q0.x = h2u(__floats2half2_rn(p[0],  p[1]));
    q0.y = h2u(__floats2half2_rn(p[2],  p[3]));
    q0.z = h2u(__floats2half2_rn(p[4],  p[5]));
    q0.w = h2u(__floats2half2_rn(p[6],  p[7]));
    q1.x = h2u(__floats2half2_rn(p[8],  p[9]));
    q1.y = h2u(__floats2half2_rn(p[10], p[11]));
    q1.z = h2u(__floats2half2_rn(p[12], p[13]));
    q1.w = h2u(__floats2half2_rn(p[14], p[15]));
    const uint32_t sw = ((uint32_t)(d & 6)) << 3;
    const uint32_t base = tbase + d*64;
    sts128(base + (((uint32_t)(kq*32     )) ^ sw), q0);
    sts128(base + (((uint32_t)(kq*32 + 16)) ^ sw), q1);
}

// ---- one layer ----
template<int K, int Nh, int SRCS, int CHUNK0, int OUT_OFF, bool LAST>
static __device__ __forceinline__ void layer_run(
    const float* __restrict__ bg, char* smem, uint32_t smem_base,
    float* __restrict__ out, int b, int tid)
{
    const float* v   = reinterpret_cast<const float*>(smem + OFF_V);
    const float* src = (Nh == 40) ? v : reinterpret_cast<const float*>(smem + OFF_H);
    float* h = reinterpret_cast<float*>(smem + OFF_H);
    constexpr int NCH = K / KC;

    const int lane = tid & 31, w = tid >> 5;
    const int g = lane >> 2, tig = lane & 3;
    const int o0 = w * 32;

    // ldmatrix lane decomposition: tile lt = lane>>3, row-in-tile lr = lane&7
    const int lt = lane >> 3, lr = lane & 7;
    const uint32_t lsw = ((uint32_t)(lr & 6)) << 3;
    // A tiles: rowgroup = lt&1 (rows +0/+8), colhalf = lt>>1  -> {a0,a1,a2,a3}
    const uint32_t aRow = (uint32_t)((lt & 1)*8 + lr) * 64;
    const uint32_t aColH = (uint32_t)(lt >> 1) * 16;
    // B tiles: rowgroup = lt>>1 (j / j+1), colhalf = lt&1     -> {b0_j,b1_j,b0_j1,b1_j1}
    const uint32_t bRow = (uint32_t)((lt >> 1)*8 + lr) * 64;
    const uint32_t bColH = (uint32_t)(lt & 1) * 16;

    float c[2][8][4];
    #pragma unroll
    for (int ot = 0; ot < 2; ot++)
        #pragma unroll
        for (int j = 0; j < 8; j++)
            #pragma unroll
            for (int r = 0; r < 4; r++) c[ot][j][r] = 0.0f;

    // stage chunk 0
    {
        const char* gsrc = reinterpret_cast<const char*>(g_w16 + (size_t)CHUNK0 * 896);
        #pragma unroll
        for (int j = 0; j < 4; j++)
            cpasync16(smem_base + OFF_W + (tid + j*NT)*16, gsrc + (tid + j*NT)*16);
        asm volatile("cp.async.commit_group;" ::: "memory");
        build_T<Nh, SRCS>(v, src, smem_base + OFF_T, 0, tid);
        asm volatile("cp.async.wait_group 0;" ::: "memory");
    }
    __syncthreads();

    for (int kc = 0; kc < NCH; kc++) {
        const int cur = kc & 1, nxt = cur ^ 1;
        const bool more = (kc + 1) < NCH;

        // async-stage next W chunk straight into smem (no regs)
        if (more) {
            const char* gsrc = reinterpret_cast<const char*>(
                g_w16 + (size_t)(CHUNK0 + kc + 1) * 896);
            uint32_t sdst = smem_base + OFF_W + nxt*WSZ;
            #pragma unroll
            for (int j = 0; j < 4; j++)
                cpasync16(sdst + (tid + j*NT)*16, gsrc + (tid + j*NT)*16);
            asm volatile("cp.async.commit_group;" ::: "memory");
        }

        // MMA on current buffers (ldmatrix fragments)
        const uint32_t Wb = smem_base + OFF_W + cur*WSZ + (uint32_t)o0*64 + aRow;
        const uint32_t Tb = smem_base + OFF_T + cur*TSZ + bRow;
        #pragma unroll
        for (int kq = 0; kq < 2; kq++) {
            uint32_t bf[16];
            const uint32_t bCol = (((uint32_t)(kq*32) + bColH) ^ lsw);
            #pragma unroll
            for (int jj = 0; jj < 4; jj++)
                ldsm4(bf[4*jj], bf[4*jj+1], bf[4*jj+2], bf[4*jj+3],
                      Tb + (uint32_t)jj*1024 + bCol);
            const uint32_t aCol = (((uint32_t)(kq*32) + aColH) ^ lsw);
            #pragma unroll
            for (int ot = 0; ot < 2; ot++) {
                uint32_t a0, a1, a2, a3;
                ldsm4(a0, a1, a2, a3, Wb + (uint32_t)ot*1024 + aCol);
                #pragma unroll
                for (int jj = 0; jj < 4; jj++) {
                    mma16816(c[ot][2*jj],   a0, a1, a2, a3, bf[4*jj],   bf[4*jj+1]);
                    mma16816(c[ot][2*jj+1], a0, a1, a2, a3, bf[4*jj+2], bf[4*jj+3]);
                }
            }
        }

        if (more) {
            build_T<Nh, SRCS>(v, src, smem_base + OFF_T + nxt*TSZ, (kc + 1)*KC, tid);
            asm volatile("cp.async.wait_group 0;" ::: "memory");
        }
        __syncthreads();
    }

    // epilogue
    #pragma unroll
    for (int ot = 0; ot < 2; ot++) {
        const int r0 = o0 + ot*16 + g, r1 = r0 + 8;
        const float bz0 = (r0 < 200) ? bg[r0] : 0.0f;
        const float bz1 = (r1 < 200) ? bg[r1] : 0.0f;
        float s0 = 0.0f, s1 = 0.0f;
        #pragma unroll
        for (int j = 0; j < 8; j++) {
            float y00 = fmaxf(c[ot][j][0] + bz0, 0.0f);
            float y01 = fmaxf(c[ot][j][1] + bz0, 0.0f);
            float y10 = fmaxf(c[ot][j][2] + bz1, 0.0f);
            float y11 = fmaxf(c[ot][j][3] + bz1, 0.0f);
            if (!LAST) {
                const int d = j*8 + 2*tig;
                if (r0 < 100) *reinterpret_cast<float2*>(h + r0*72 + d) = make_float2(y00, y01);
                if (r1 < 100) *reinterpret_cast<float2*>(h + r1*72 + d) = make_float2(y10, y11);
            }
            s0 += y00 + y01;
            s1 += y10 + y11;
        }
        s0 += __shfl_xor_sync(0xFFFFFFFFu, s0, 1);
        s0 += __shfl_xor_sync(0xFFFFFFFFu, s0, 2);
        s1 += __shfl_xor_sync(0xFFFFFFFFu, s1, 1);
        s1 += __shfl_xor_sync(0xFFFFFFFFu, s1, 2);
        if (tig == 0) {
            if (LAST) {
                if (r0 < 200) out[b*400 + 200 + r0] = s0;
                if (r1 < 200) out[b*400 + 200 + r1] = s1;
            } else {
                if (r0 >= 100 && r0 < 200) out[b*400 + OUT_OFF + (r0 - 100)] = s0;
                if (r1 >= 100 && r1 < 200) out[b*400 + OUT_OFF + (r1 - 100)] = s1;
            }
        }
    }
    __syncthreads();   // h fully written before next layer's build_T reads it
}

__global__ void __launch_bounds__(NT, 2)
_CIN_41575283425691_kernel(const float* __restrict__ x,
                           const float* __restrict__ b1,
                           const float* __restrict__ b2,
                           const float* __restrict__ b3,
                           float* __restrict__ out)
{
    extern __shared__ char smem[];
    const uint32_t smem_base = smem_u32(smem);
    const int tid = threadIdx.x;
    const int b   = blockIdx.x;

    float* v = reinterpret_cast<float*>(smem + OFF_V);
    const float* xb = x + b*2560;
    for (int i = tid; i < 2560; i += NT) v[i] = xb[i];
    __syncthreads();

    layer_run<1600,  40, 64,   0,   0, false>(b1, smem, smem_base, out, b, tid);
    layer_run<4000, 100, 72,  50, 100, false>(b2, smem, smem_base, out, b, tid);
    layer_run<4000, 100, 72, 175,   0, true >(b3, smem, smem_base, out, b, tid);
}

extern "C" void kernel_launch(void* const* d_in, const int* in_sizes, int n_in,
                              void* d_out, int out_size)
{
    const float* x  = (const float*)d_in[0];
    const float* w1 = (const float*)d_in[1];
    const float* b1 = (const float*)d_in[2];
    const float* w2 = (const float*)d_in[3];
    const float* b2 = (const float*)d_in[4];
    const float* w3 = (const float*)d_in[5];
    const float* b3 = (const float*)d_in[6];
    float* out = (float*)d_out;

    _CIN_prep_kernel<<<300, 256>>>(w1, w2, w3);

    cudaFuncSetAttribute(_CIN_41575283425691_kernel,
                         cudaFuncAttributeMaxDynamicSharedMemorySize, SMEM_BYTES);
    _CIN_41575283425691_kernel<<<512, NT, SMEM_BYTES>>>(x, b1, b2, b3, out);
}

// round 10
// speedup vs baseline: 12.2497x; 1.0291x over previous
#include <cuda_runtime.h>
#include <cuda_fp16.h>
#include <cstdint>

#define NT   224
#define SKC  64                    // superchunk k extent
#define WSZ  28672                 // 224 rows x 128B, one W superchunk tile
#define TSZ  8192                  // 64 rows x 128B, one T superchunk tile

// smem byte map
#define OFF_V  0                   // v: 2560 f32 (stride 64)        = 10240
#define OFF_H  10240               // h: 100 x 72 f32 (padded)       = 28800
#define OFF_W  39040               // 2 x WSZ (128B aligned)
#define OFF_T  (OFF_W + 2*WSZ)     // 96384 (128B aligned)
#define SMEM_BYTES (OFF_T + 2*TSZ) // 112768  (x2 CTA = 225536 <= 228KB)

// Pre-converted W: 151 superchunks x 1792 uint4 (28672B each): fp16, k-linear 128B rows,
// full swizzle: byte_col16 ^= (row & 7) << 4 ; k-tail beyond K zero-padded.
__device__ uint4 g_w16[151 * 1792];

static __device__ __forceinline__ uint32_t smem_u32(const void* p) {
    uint32_t a;
    asm("{ .reg .u64 t; cvta.to.shared.u64 t, %1; cvt.u32.u64 %0, t; }" : "=r"(a) : "l"(p));
    return a;
}
static __device__ __forceinline__ void sts128(uint32_t a, uint4 v) {
    asm volatile("st.shared.v4.b32 [%0], {%1,%2,%3,%4};"
                 :: "r"(a), "r"(v.x), "r"(v.y), "r"(v.z), "r"(v.w));
}
static __device__ __forceinline__ void ldsm4(uint32_t& r0, uint32_t& r1,
                                             uint32_t& r2, uint32_t& r3, uint32_t a) {
    asm volatile("ldmatrix.sync.aligned.m8n8.x4.shared.b16 {%0,%1,%2,%3}, [%4];"
                 : "=r"(r0), "=r"(r1), "=r"(r2), "=r"(r3) : "r"(a));
}
static __device__ __forceinline__ void cpasync16(uint32_t s, const void* g) {
    asm volatile("cp.async.cg.shared.global [%0], [%1], 16;"
                 :: "r"(s), "l"(__cvta_generic_to_global(g)) : "memory");
}
static __device__ __forceinline__ void mma16816(float* c, uint32_t a0, uint32_t a1,
                                                uint32_t a2, uint32_t a3,
                                                uint32_t b0, uint32_t b1) {
    asm volatile(
        "mma.sync.aligned.m16n8k16.row.col.f32.f16.f16.f32 "
        "{%0,%1,%2,%3}, {%4,%5,%6,%7}, {%8,%9}, {%0,%1,%2,%3};"
        : "+f"(c[0]), "+f"(c[1]), "+f"(c[2]), "+f"(c[3])
        : "r"(a0), "r"(a1), "r"(a2), "r"(a3), "r"(b0), "r"(b1));
}
static __device__ __forceinline__ uint32_t h2u(__half2 h) {
    return *reinterpret_cast<uint32_t*>(&h);
}

// ---- prep: W fp32 -> fp16 superchunk tiles, 128B rows, full swizzle, zero-padded ----
__global__ void _CIN_prep_kernel(const float* __restrict__ w1,
                                 const float* __restrict__ w2,
                                 const float* __restrict__ w3) {
    int sc = blockIdx.x;           // global superchunk 0..150
    const float* W; int K, scl;
    if (sc < 25)      { W = w1; K = 1600; scl = sc; }
    else if (sc < 88) { W = w2; K = 4000; scl = sc - 25; }
    else              { W = w3; K = 4000; scl = sc - 88; }
    const int kbase = scl * SKC;
    char* dst = reinterpret_cast<char*>(g_w16 + (size_t)sc * 1792);
    for (int q = threadIdx.x; q < 1792; q += 256) {   // 224 rows x 8 16B-quads
        int row = q >> 3, qq = q & 7;                 // quad qq = k-local 8qq..8qq+7
        int k = kbase + qq*8;
        uint4 val = make_uint4(0, 0, 0, 0);
        if (row < 200 && k < K) {
            const float* s = W + row*K + k;
            val.x = h2u(__floats2half2_rn(s[0], s[1]));
            val.y = h2u(__floats2half2_rn(s[2], s[3]));
            val.z = h2u(__floats2half2_rn(s[4], s[5]));
            val.w = h2u(__floats2half2_rn(s[6], s[7]));
        }
        uint32_t byte = row*128 + (((uint32_t)(qq*16)) ^ (((uint32_t)(row & 7)) << 4));
        *reinterpret_cast<uint4*>(dst + byte) = val;
    }
}

// ---- T superchunk build: T[d][k] fp16, 128B rows, full swizzle; all NT threads ----
template<int K, int Nh, int SRCS>
static __device__ __forceinline__ void build_T(const float* __restrict__ v,
                                               const float* __restrict__ src,
                                               uint32_t tbase, int k0, int tid) {
    for (int i = tid; i < 256; i += NT) {     // task = (d, kq16)
        const int d = i & 63, kq = i >> 6;
        const int kb = k0 + kq*16;
        if (kb >= K) continue;                // zero-padded W covers the tail
        int m = kb / Nh;
        int n = kb - m*Nh;
        float vm = v[m*64 + d];
        float p[16];
        #pragma unroll
        for (int t = 0; t < 16; t++) {
            if (n == Nh) { n = 0; m++; vm = v[m*64 + d]; }
            p[t] = vm * src[n*SRCS + d];
            n++;
        }
        uint4 q0, q1;
        q0.x = h2u(__floats2half2_rn(p[0],  p[1]));
        q0.y = h2u(__floats2half2_rn(p[2],  p[3]));
        q0.z = h2u(__floats2half2_rn(p[4],  p[5]));
        q0.w = h2u(__floats2half2_rn(p[6],  p[7]));
        q1.x = h2u(__floats2half2_rn(p[8],  p[9]));
        q1.y = h2u(__floats2half2_rn(p[10], p[11]));
        q1.z = h2u(__floats2half2_rn(p[12], p[13]));
        q1.w = h2u(__floats2half2_rn(p[14], p[15]));
        const uint32_t sw = ((uint32_t)(d & 7)) << 4;
        const uint32_t base = tbase + d*128;
        sts128(base + (((uint32_t)(kq*32     )) ^ sw), q0);
        sts128(base + (((uint32_t)(kq*32 + 16)) ^ sw), q1);
    }
}

// ---- one layer ----
template<int K, int Nh, int SRCS, int SC0, int NSC, int OUT_OFF, bool LAST>
static __device__ __forceinline__ void layer_run(
    const float* __restrict__ bg, char* smem, uint32_t smem_base,
    float* __restrict__ out, int b, int tid)
{
    const float* v   = reinterpret_cast<const float*>(smem + OFF_V);
    const float* src = (Nh == 40) ? v : reinterpret_cast<const float*>(smem + OFF_H);
    float* h = reinterpret_cast<float*>(smem + OFF_H);

    const int lane = tid & 31, w = tid >> 5;
    const int g = lane >> 2, tig = lane & 3;
    const int o0 = w * 32;

    // ldmatrix lane decomposition
    const int lt = lane >> 3, lr = lane & 7;
    const uint32_t lsw = ((uint32_t)lr) << 4;
    const uint32_t aRowB = (uint32_t)(o0 + (lt & 1)*8 + lr) * 128;
    const uint32_t aColH = (uint32_t)(lt >> 1) * 16;
    const uint32_t bRowB = (uint32_t)((lt >> 1)*8 + lr) * 128;
    const uint32_t bColH = (uint32_t)(lt & 1) * 16;

    float c[2][8][4];
    #pragma unroll
    for (int ot = 0; ot < 2; ot++)
        #pragma unroll
        for (int j = 0; j < 8; j++)
            #pragma unroll
            for (int r = 0; r < 4; r++) c[ot][j][r] = 0.0f;

    // stage superchunk 0
    {
        const char* gsrc = reinterpret_cast<const char*>(g_w16 + (size_t)SC0 * 1792);
        #pragma unroll
        for (int j = 0; j < 8; j++)
            cpasync16(smem_base + OFF_W + (tid + j*NT)*16, gsrc + (tid + j*NT)*16);
        asm volatile("cp.async.commit_group;" ::: "memory");
        build_T<K, Nh, SRCS>(v, src, smem_base + OFF_T, 0, tid);
        asm volatile("cp.async.wait_group 0;" ::: "memory");
    }
    __syncthreads();

    for (int sc = 0; sc < NSC; sc++) {
        const int cur = sc & 1, nxt = cur ^ 1;
        const bool more = (sc + 1) < NSC;

        // producers first: async W stage + T build for next superchunk (overlaps MMA issue)
        if (more) {
            const char* gsrc = reinterpret_cast<const char*>(
                g_w16 + (size_t)(SC0 + sc + 1) * 1792);
            uint32_t sdst = smem_base + OFF_W + nxt*WSZ;
            #pragma unroll
            for (int j = 0; j < 8; j++)
                cpasync16(sdst + (tid + j*NT)*16, gsrc + (tid + j*NT)*16);
            asm volatile("cp.async.commit_group;" ::: "memory");
            build_T<K, Nh, SRCS>(v, src, smem_base + OFF_T + nxt*TSZ, (sc + 1)*SKC, tid);
        }

        // MMA on current buffers: 4 kq x (4 B-ldsm + 2 A-ldsm + 16 MMA)
        const uint32_t Wb = smem_base + OFF_W + cur*WSZ + aRowB;
        const uint32_t Tb = smem_base + OFF_T + cur*TSZ + bRowB;
        #pragma unroll
        for (int kq = 0; kq < 4; kq++) {
            uint32_t bf[16];
            const uint32_t bCol = (((uint32_t)(kq*32) + bColH) ^ lsw);
            #pragma unroll
            for (int jj = 0; jj < 4; jj++)
                ldsm4(bf[4*jj], bf[4*jj+1], bf[4*jj+2], bf[4*jj+3],
                      Tb + (uint32_t)jj*2048 + bCol);
            const uint32_t aCol = (((uint32_t)(kq*32) + aColH) ^ lsw);
            #pragma unroll
            for (int ot = 0; ot < 2; ot++) {
                uint32_t a0, a1, a2, a3;
                ldsm4(a0, a1, a2, a3, Wb + (uint32_t)ot*2048 + aCol);
                #pragma unroll
                for (int jj = 0; jj < 4; jj++) {
                    mma16816(c[ot][2*jj],   a0, a1, a2, a3, bf[4*jj],   bf[4*jj+1]);
                    mma16816(c[ot][2*jj+1], a0, a1, a2, a3, bf[4*jj+2], bf[4*jj+3]);
                }
            }
        }

        if (more)
            asm volatile("cp.async.wait_group 0;" ::: "memory");
        __syncthreads();
    }

    // epilogue
    #pragma unroll
    for (int ot = 0; ot < 2; ot++) {
        const int r0 = o0 + ot*16 + g, r1 = r0 + 8;
        const float bz0 = (r0 < 200) ? bg[r0] : 0.0f;
        const float bz1 = (r1 < 200) ? bg[r1] : 0.0f;
        float s0 = 0.0f, s1 = 0.0f;
        #pragma unroll
        for (int j = 0; j < 8; j++) {
            float y00 = fmaxf(c[ot][j][0] + bz0, 0.0f);
            float y01 = fmaxf(c[ot][j][1] + bz0, 0.0f);
            float y10 = fmaxf(c[ot][j][2] + bz1, 0.0f);
            float y11 = fmaxf(c[ot][j][3] + bz1, 0.0f);
            if (!LAST) {
                const int d = j*8 + 2*tig;
                if (r0 < 100) *reinterpret_cast<float2*>(h + r0*72 + d) = make_float2(y00, y01);
                if (r1 < 100) *reinterpret_cast<float2*>(h + r1*72 + d) = make_float2(y10, y11);
            }
            s0 += y00 + y01;
            s1 += y10 + y11;
        }
        s0 += __shfl_xor_sync(0xFFFFFFFFu, s0, 1);
        s0 += __shfl_xor_sync(0xFFFFFFFFu, s0, 2);
        s1 += __shfl_xor_sync(0xFFFFFFFFu, s1, 1);
        s1 += __shfl_xor_sync(0xFFFFFFFFu, s1, 2);
        if (tig == 0) {
            if (LAST) {
                if (r0 < 200) out[b*400 + 200 + r0] = s0;
                if (r1 < 200) out[b*400 + 200 + r1] = s1;
            } else {
                if (r0 >= 100 && r0 < 200) out[b*400 + OUT_OFF + (r0 - 100)] = s0;
                if (r1 >= 100 && r1 < 200) out[b*400 + OUT_OFF + (r1 - 100)] = s1;
            }
        }
    }
    __syncthreads();   // h fully written before next layer's build_T reads it
}

__global__ void __launch_bounds__(NT, 2)
_CIN_41575283425691_kernel(const float* __restrict__ x,
                           const float* __restrict__ b1,
                           const float* __restrict__ b2,
                           const float* __restrict__ b3,
                           float* __restrict__ out)
{
    extern __shared__ char smem[];
    const uint32_t smem_base = smem_u32(smem);
    const int tid = threadIdx.x;
    const int b   = blockIdx.x;

    float* v = reinterpret_cast<float*>(smem + OFF_V);
    const float* xb = x + b*2560;
    for (int i = tid; i < 2560; i += NT) v[i] = xb[i];
    __syncthreads();

    layer_run<1600,  40, 64,  0, 25,   0, false>(b1, smem, smem_base, out, b, tid);
    layer_run<4000, 100, 72, 25, 63, 100, false>(b2, smem, smem_base, out, b, tid);
    layer_run<4000, 100, 72, 88, 63,   0, true >(b3, smem, smem_base, out, b, tid);
}

extern "C" void kernel_launch(void* const* d_in, const int* in_sizes, int n_in,
                              void* d_out, int out_size)
{
    const float* x  = (const float*)d_in[0];
    const float* w1 = (const float*)d_in[1];
    const float* b1 = (const float*)d_in[2];
    const float* w2 = (const float*)d_in[3];
    const float* b2 = (const float*)d_in[4];
    const float* w3 = (const float*)d_in[5];
    const float* b3 = (const float*)d_in[6];
    float* out = (float*)d_out;

    _CIN_prep_kernel<<<151, 256>>>(w1, w2, w3);

    cudaFuncSetAttribute(_CIN_41575283425691_kernel,
                         cudaFuncAttributeMaxDynamicSharedMemorySize, SMEM_BYTES);
    _CIN_41575283425691_kernel<<<512, NT, SMEM_BYTES>>>(x, b1, b2, b3, out);
}